// round 1
// baseline (speedup 1.0000x reference)
#include <cuda_runtime.h>
#include <math.h>

#define NN    4096
#define INF_  512
#define HID   8
#define OUTF  256
#define MAXD  128

// ---------------- scratch (static device globals; no runtime allocation) ----
__device__ int   g_deg[NN];
__device__ int   g_nbr[NN * MAXD];
__device__ float g_h[NN * HID];      // x @ W1
__device__ float g_dst1[NN];         // h @ a1[8:16]
__device__ float g_ph[NN * HID];     // softmax(dst1)[j] * h[j]
__device__ float g_h2v[NN];          // h1 @ W2
__device__ float g_d2[NN];           // h2 * a2[1]
__device__ float g_q[NN];            // softmax(d2)[j] * h2[j]
__device__ int   g_rows[2][NN];      // row lists: [0]=mask==1 (use y1,Wa), [1]=mask==0 (use y3,Wc)
__device__ int   g_cnt[2];
__device__ float g_y1[NN * INF_];    // adj   @ x
__device__ float g_y2[NN * INF_];    // adj^2 @ x
__device__ float g_y3[NN * INF_];    // adj^3 @ x

// ---------------- 1) build neighbor lists (deterministic order) -------------
__global__ void k_build(const float* __restrict__ adj) {
    int row = blockIdx.x;
    int t   = threadIdx.x;           // 256 threads
    const float4* ar = (const float4*)(adj + (size_t)row * NN);

    float4 v[4];
    int cnt = 0;
#pragma unroll
    for (int i = 0; i < 4; i++) {
        v[i] = ar[t + i * 256];
        cnt += (v[i].x != 0.f) + (v[i].y != 0.f) + (v[i].z != 0.f) + (v[i].w != 0.f);
    }

    __shared__ int sc[256];
    sc[t] = cnt;
    __syncthreads();
    for (int d = 1; d < 256; d <<= 1) {
        int val = (t >= d) ? sc[t - d] : 0;
        __syncthreads();
        if (t >= d) sc[t] += val;
        __syncthreads();
    }
    int pos   = sc[t] - cnt;   // exclusive prefix
    int total = sc[255];

    int* nb = g_nbr + (size_t)row * MAXD;
#pragma unroll
    for (int i = 0; i < 4; i++) {
        int base = (t + i * 256) * 4;
        if (v[i].x != 0.f) { if (pos < MAXD) nb[pos] = base + 0; pos++; }
        if (v[i].y != 0.f) { if (pos < MAXD) nb[pos] = base + 1; pos++; }
        if (v[i].z != 0.f) { if (pos < MAXD) nb[pos] = base + 2; pos++; }
        if (v[i].w != 0.f) { if (pos < MAXD) nb[pos] = base + 3; pos++; }
    }
    if (t == 0) g_deg[row] = total < MAXD ? total : MAXD;
    if (row == 0 && t < 2) g_cnt[t] = 0;   // reset list counters every launch
}

// ---------------- 2) h = x @ W1, dst1 = h @ a1[HID:] (warp per row) ---------
__global__ void k_h(const float* __restrict__ x, const float* __restrict__ W1,
                    const float* __restrict__ a1) {
    int lane = threadIdx.x & 31;
    int row  = blockIdx.x * 8 + (threadIdx.x >> 5);
    const float* xr = x + (size_t)row * INF_;

    float acc[HID];
#pragma unroll
    for (int f = 0; f < HID; f++) acc[f] = 0.f;

    for (int k = lane; k < INF_; k += 32) {
        float xv = xr[k];
        float4 wA = *(const float4*)(W1 + k * HID);
        float4 wB = *(const float4*)(W1 + k * HID + 4);
        acc[0] += xv * wA.x; acc[1] += xv * wA.y; acc[2] += xv * wA.z; acc[3] += xv * wA.w;
        acc[4] += xv * wB.x; acc[5] += xv * wB.y; acc[6] += xv * wB.z; acc[7] += xv * wB.w;
    }
#pragma unroll
    for (int f = 0; f < HID; f++)
        for (int o = 16; o; o >>= 1) acc[f] += __shfl_xor_sync(0xffffffffu, acc[f], o);

    if (lane == 0) {
        float d = 0.f;
#pragma unroll
        for (int f = 0; f < HID; f++) {
            g_h[row * HID + f] = acc[f];
            d += acc[f] * a1[HID + f];
        }
        g_dst1[row] = d;
    }
}

// ---------------- 3) softmax over dst1 -> ph = p * h (one block) ------------
__global__ void k_softmax1() {
    __shared__ float sred[32];
    __shared__ float sbc[2];
    int t = threadIdx.x;  // 1024

    float m = -1e30f;
    for (int i = t; i < NN; i += 1024) m = fmaxf(m, g_dst1[i]);
    for (int o = 16; o; o >>= 1) m = fmaxf(m, __shfl_xor_sync(0xffffffffu, m, o));
    if ((t & 31) == 0) sred[t >> 5] = m;
    __syncthreads();
    if (t < 32) {
        float v = sred[t];
        for (int o = 16; o; o >>= 1) v = fmaxf(v, __shfl_xor_sync(0xffffffffu, v, o));
        if (t == 0) sbc[0] = v;
    }
    __syncthreads();
    float M = sbc[0];

    float s = 0.f;
    for (int i = t; i < NN; i += 1024) s += expf(g_dst1[i] - M);
    for (int o = 16; o; o >>= 1) s += __shfl_xor_sync(0xffffffffu, s, o);
    if ((t & 31) == 0) sred[t >> 5] = s;
    __syncthreads();
    if (t < 32) {
        float v = sred[t];
        for (int o = 16; o; o >>= 1) v += __shfl_xor_sync(0xffffffffu, v, o);
        if (t == 0) sbc[1] = v;
    }
    __syncthreads();
    float inv = 1.f / sbc[1];

    for (int i = t; i < NN; i += 1024) {
        float p = expf(g_dst1[i] - M) * inv;
#pragma unroll
        for (int f = 0; f < HID; f++) g_ph[i * HID + f] = p * g_h[i * HID + f];
    }
}

// ---------------- 4) h1 = elu(adj @ ph); h2 = h1@W2; d2 = h2*a2[1] ----------
__global__ void k_gat1(const float* __restrict__ W2, const float* __restrict__ a2) {
    int lane = threadIdx.x & 31;
    int row  = blockIdx.x * 8 + (threadIdx.x >> 5);
    int deg  = g_deg[row];
    const int* nb = g_nbr + (size_t)row * MAXD;

    float acc[HID];
#pragma unroll
    for (int f = 0; f < HID; f++) acc[f] = 0.f;

    for (int t = lane; t < deg; t += 32) {
        int j = nb[t];
        float4 A = *(const float4*)(g_ph + j * HID);
        float4 B = *(const float4*)(g_ph + j * HID + 4);
        acc[0] += A.x; acc[1] += A.y; acc[2] += A.z; acc[3] += A.w;
        acc[4] += B.x; acc[5] += B.y; acc[6] += B.z; acc[7] += B.w;
    }
#pragma unroll
    for (int f = 0; f < HID; f++)
        for (int o = 16; o; o >>= 1) acc[f] += __shfl_xor_sync(0xffffffffu, acc[f], o);

    if (lane == 0) {
        float h2 = 0.f;
#pragma unroll
        for (int f = 0; f < HID; f++) {
            float v = acc[f];
            v = v > 0.f ? v : (expf(v) - 1.f);   // elu
            h2 += v * W2[f];
        }
        g_h2v[row] = h2;
        g_d2[row]  = h2 * a2[1];
    }
}

// ---------------- 5) softmax over d2 -> q = p2 * h2 (one block) -------------
__global__ void k_softmax2() {
    __shared__ float sred[32];
    __shared__ float sbc[2];
    int t = threadIdx.x;

    float m = -1e30f;
    for (int i = t; i < NN; i += 1024) m = fmaxf(m, g_d2[i]);
    for (int o = 16; o; o >>= 1) m = fmaxf(m, __shfl_xor_sync(0xffffffffu, m, o));
    if ((t & 31) == 0) sred[t >> 5] = m;
    __syncthreads();
    if (t < 32) {
        float v = sred[t];
        for (int o = 16; o; o >>= 1) v = fmaxf(v, __shfl_xor_sync(0xffffffffu, v, o));
        if (t == 0) sbc[0] = v;
    }
    __syncthreads();
    float M = sbc[0];

    float s = 0.f;
    for (int i = t; i < NN; i += 1024) s += expf(g_d2[i] - M);
    for (int o = 16; o; o >>= 1) s += __shfl_xor_sync(0xffffffffu, s, o);
    if ((t & 31) == 0) sred[t >> 5] = s;
    __syncthreads();
    if (t < 32) {
        float v = sred[t];
        for (int o = 16; o; o >>= 1) v += __shfl_xor_sync(0xffffffffu, v, o);
        if (t == 0) sbc[1] = v;
    }
    __syncthreads();
    float inv = 1.f / sbc[1];

    for (int i = t; i < NN; i += 1024) {
        float p = expf(g_d2[i] - M) * inv;
        g_q[i] = p * g_h2v[i];
    }
}

// ---------------- 6) scores -> mask -> row lists ----------------------------
__global__ void k_mask() {
    int row = blockIdx.x * blockDim.x + threadIdx.x;
    int deg = g_deg[row];
    const int* nb = g_nbr + (size_t)row * MAXD;
    float s = 0.f;
    for (int t = 0; t < deg; t++) s += g_q[nb[t]];
    float sc = s > 0.f ? s : (expf(s) - 1.f);   // elu
    int which = (sc > 0.7f) ? 0 : 1;
    int pos = atomicAdd(&g_cnt[which], 1);
    g_rows[which][pos] = row;
}

// ---------------- 7) SpMM: dst[row] = sum over neighbors of src[j] ----------
// mode 0: x -> y1 ; mode 1: y1 -> y2 ; mode 2: y2 -> y3
__global__ void k_spmm(const float* __restrict__ xin, int mode) {
    const float* __restrict__ src =
        (mode == 0) ? xin : ((mode == 1) ? (const float*)g_y1 : (const float*)g_y2);
    float* dst = (mode == 0) ? g_y1 : ((mode == 1) ? g_y2 : g_y3);

    int row = blockIdx.x;
    __shared__ int nbs[MAXD];
    int deg = g_deg[row];
    for (int i = threadIdx.x; i < deg; i += 128) nbs[i] = g_nbr[(size_t)row * MAXD + i];
    __syncthreads();

    int c = threadIdx.x << 2;   // 128 threads * float4 = 512 cols
    float4 acc = make_float4(0.f, 0.f, 0.f, 0.f);
    int k = 0;
    for (; k + 4 <= deg; k += 4) {
        const float4 a0 = *(const float4*)(src + (size_t)nbs[k]     * INF_ + c);
        const float4 a1 = *(const float4*)(src + (size_t)nbs[k + 1] * INF_ + c);
        const float4 a2 = *(const float4*)(src + (size_t)nbs[k + 2] * INF_ + c);
        const float4 a3 = *(const float4*)(src + (size_t)nbs[k + 3] * INF_ + c);
        acc.x += (a0.x + a1.x) + (a2.x + a3.x);
        acc.y += (a0.y + a1.y) + (a2.y + a3.y);
        acc.z += (a0.z + a1.z) + (a2.z + a3.z);
        acc.w += (a0.w + a1.w) + (a2.w + a3.w);
    }
    for (; k < deg; k++) {
        const float4 a = *(const float4*)(src + (size_t)nbs[k] * INF_ + c);
        acc.x += a.x; acc.y += a.y; acc.z += a.z; acc.w += a.w;
    }
    *(float4*)(dst + (size_t)row * INF_ + c) = acc;
}

// ---------------- 8) routed GEMM: out[r] = y@W + b per row list -------------
// which==0: rows with mask==1, A=g_y1, W = W_sgc[   0: 512]
// which==1: rows with mask==0, A=g_y3, W = W_sgc[1024:1536]
__global__ void k_gemm(const float* __restrict__ Wsgc, const float* __restrict__ bias,
                       float* __restrict__ out, int which) {
    __shared__ float As[16][64];
    __shared__ float Bs[16][64];
    __shared__ int   ridx[64];

    int cnt   = g_cnt[which];
    int rbase = blockIdx.x * 64;
    if (rbase >= cnt) return;

    const float* A = which ? g_y3 : g_y1;
    const float* B = Wsgc + (which ? (size_t)1024 * OUTF : 0) + blockIdx.y * 64;

    int tid = threadIdx.x;   // 256
    if (tid < 64) {
        int li = rbase + tid;
        ridx[tid] = (li < cnt) ? g_rows[which][li] : -1;
    }
    __syncthreads();

    int am = tid >> 2;            // 0..63 : row in tile (A load)
    int ak = (tid & 3) * 4;       // 0,4,8,12 : k sub-offset (A load)
    int bk = tid >> 4;            // 0..15 : k row (B load)
    int bn = (tid & 15) * 4;      // 0..60 : col (B load)

    int arow = ridx[am];
    const float* aptr = (arow >= 0) ? (A + (size_t)arow * INF_ + ak) : A;

    float acc[4][4];
#pragma unroll
    for (int i = 0; i < 4; i++)
#pragma unroll
        for (int j = 0; j < 4; j++) acc[i][j] = 0.f;

    int ty = tid >> 4;   // 0..15 : row group for compute
    int tx = tid & 15;   // 0..15 : col group for compute

    for (int k0 = 0; k0 < INF_; k0 += 16) {
        float4 av = (arow >= 0) ? *(const float4*)(aptr + k0) : make_float4(0.f, 0.f, 0.f, 0.f);
        float4 bv = *(const float4*)(B + (size_t)(k0 + bk) * OUTF + bn);
        __syncthreads();
        As[ak + 0][am] = av.x; As[ak + 1][am] = av.y;
        As[ak + 2][am] = av.z; As[ak + 3][am] = av.w;
        *(float4*)&Bs[bk][bn] = bv;
        __syncthreads();
#pragma unroll
        for (int kk = 0; kk < 16; kk++) {
            float4 a4 = *(const float4*)&As[kk][ty * 4];
            float4 b4 = *(const float4*)&Bs[kk][tx * 4];
            acc[0][0] += a4.x * b4.x; acc[0][1] += a4.x * b4.y; acc[0][2] += a4.x * b4.z; acc[0][3] += a4.x * b4.w;
            acc[1][0] += a4.y * b4.x; acc[1][1] += a4.y * b4.y; acc[1][2] += a4.y * b4.z; acc[1][3] += a4.y * b4.w;
            acc[2][0] += a4.z * b4.x; acc[2][1] += a4.z * b4.y; acc[2][2] += a4.z * b4.z; acc[2][3] += a4.z * b4.w;
            acc[3][0] += a4.w * b4.x; acc[3][1] += a4.w * b4.y; acc[3][2] += a4.w * b4.z; acc[3][3] += a4.w * b4.w;
        }
    }

    int cbase = blockIdx.y * 64 + tx * 4;
#pragma unroll
    for (int i = 0; i < 4; i++) {
        int r = ridx[ty * 4 + i];
        if (r >= 0) {
#pragma unroll
            for (int j = 0; j < 4; j++)
                out[(size_t)r * OUTF + cbase + j] = acc[i][j] + bias[cbase + j];
        }
    }
}

// ---------------- launcher --------------------------------------------------
extern "C" void kernel_launch(void* const* d_in, const int* in_sizes, int n_in,
                              void* d_out, int out_size) {
    const float* x    = (const float*)d_in[0];
    const float* adj  = (const float*)d_in[1];
    const float* W1   = (const float*)d_in[2];
    const float* a1   = (const float*)d_in[3];
    const float* W2   = (const float*)d_in[4];
    const float* a2   = (const float*)d_in[5];
    const float* Wsgc = (const float*)d_in[6];
    const float* bsgc = (const float*)d_in[7];
    float* out = (float*)d_out;

    k_build<<<NN, 256>>>(adj);
    k_h<<<NN / 8, 256>>>(x, W1, a1);
    k_softmax1<<<1, 1024>>>();
    k_gat1<<<NN / 8, 256>>>(W2, a2);
    k_softmax2<<<1, 1024>>>();
    k_mask<<<NN / 256, 256>>>();
    k_spmm<<<NN, 128>>>(x, 0);        // y1 = adj   @ x
    k_spmm<<<NN, 128>>>(x, 1);        // y2 = adj^2 @ x
    k_spmm<<<NN, 128>>>(x, 2);        // y3 = adj^3 @ x
    k_gemm<<<dim3(64, 4), 256>>>(Wsgc, bsgc, out, 0);
    k_gemm<<<dim3(64, 4), 256>>>(Wsgc, bsgc, out, 1);
}